// round 13
// baseline (speedup 1.0000x reference)
#include <cuda_runtime.h>
#include <math.h>
#include <stdint.h>

// out[n][m] = -sqrt(max(||a_n||^2 + ||b_m||^2 - 2 <a_n,b_m>, 0))
// Round 12 (= round 11 resubmit; infra failure, kernel never ran):
// combine the round-8 arithmetic intensity (warp tile 64x64, 8 MAC/B of
// LDSM traffic) with the round-10 occupancy (2 CTAs/SM):
//  - CTA 128x128, 128 threads (4 warps, 2m x 2n), warp tile 64x64.
//  - 3-stage cp.async ring (K-chunks of 32), 96KB smem -> 2 CTAs/SM.
//  - Epilogue staged through conflict-free smem -> coalesced STG.128.

#define DDIM 128
#define TM   128
#define TN   128

__device__ float g_a2[8192];
__device__ float g_b2[8192];

__global__ void norms_kernel(const float* __restrict__ A,
                             const float* __restrict__ B, int N, int M) {
    int row  = blockIdx.x * 8 + (threadIdx.x >> 5);
    int lane = threadIdx.x & 31;
    const float* src;
    float* dst;
    if (row < N) { src = A + (size_t)row * DDIM; dst = g_a2 + row; }
    else {
        int r = row - N;
        if (r >= M) return;
        src = B + (size_t)r * DDIM; dst = g_b2 + r;
    }
    float4 v = reinterpret_cast<const float4*>(src)[lane];
    float s = v.x * v.x + v.y * v.y + v.z * v.z + v.w * v.w;
    #pragma unroll
    for (int o = 16; o; o >>= 1) s += __shfl_xor_sync(0xffffffffu, s, o);
    if (lane == 0) *dst = s;
}

__device__ __forceinline__ uint32_t smem_u32(const void* p) {
    uint32_t a;
    asm("{ .reg .u64 t; cvta.to.shared.u64 t, %1; cvt.u32.u64 %0, t; }"
        : "=r"(a) : "l"(p));
    return a;
}
__device__ __forceinline__ void mma_tf32(float* c, const uint32_t* a,
                                         const uint32_t* b) {
    asm volatile(
        "mma.sync.aligned.m16n8k8.row.col.f32.tf32.tf32.f32 "
        "{%0,%1,%2,%3}, {%4,%5,%6,%7}, {%8,%9}, {%0,%1,%2,%3};"
        : "+f"(c[0]), "+f"(c[1]), "+f"(c[2]), "+f"(c[3])
        : "r"(a[0]), "r"(a[1]), "r"(a[2]), "r"(a[3]), "r"(b[0]), "r"(b[1]));
}
__device__ __forceinline__ void ldsm_x4(uint32_t* r, uint32_t addr) {
    asm volatile(
        "ldmatrix.sync.aligned.m8n8.x4.shared.b16 {%0,%1,%2,%3}, [%4];"
        : "=r"(r[0]), "=r"(r[1]), "=r"(r[2]), "=r"(r[3]) : "r"(addr));
}
__device__ __forceinline__ void cp_async16(uint32_t dst, const void* src) {
    asm volatile("cp.async.cg.shared.global [%0], [%1], 16;"
                 :: "r"(dst), "l"(src));
}
#define CP_COMMIT() asm volatile("cp.async.commit_group;" ::: "memory")
#define CP_WAIT(n)  asm volatile("cp.async.wait_group %0;" :: "n"(n) : "memory")

// FFMA-only sqrt: magic rsqrt + 2 Newton steps; 0 -> 0 (no NaN).
__device__ __forceinline__ float fast_sqrt(float x) {
    float y = __int_as_float(0x5f3759df - (__float_as_int(x) >> 1));
    float h = 0.5f * x;
    y = y * (1.5f - h * y * y);
    y = y * (1.5f - h * y * y);
    return x * y;
}

// Ring: 3 stages x 8192 floats (A 128x32 at +0, B 128x32 at +4096 floats).
// Then a2s[128], b2s[128]. Epilogue staging reuses the ring.
#define RING_F      8192
#define A2S_F       24576
#define B2S_F       24704
#define SMEM_FLOATS 24832
#define SMEM_BYTES  (SMEM_FLOATS * 4)
#define STG_STRIDE  72

__global__ __launch_bounds__(128, 2)
void dist_mma_kernel(const float* __restrict__ A, const float* __restrict__ B,
                     float* __restrict__ out, int N, int M) {
    extern __shared__ float smem[];
    float* a2s = smem + A2S_F;
    float* b2s = smem + B2S_F;

    const int tid  = threadIdx.x;
    const int wid  = tid >> 5;      // 0..3
    const int lane = tid & 31;
    const int g    = lane >> 2;
    const int tig  = lane & 3;
    const int row0 = blockIdx.y * TM;
    const int col0 = blockIdx.x * TN;

    const uint32_t SA = smem_u32(smem);

    a2s[tid] = g_a2[row0 + tid];    // tid 0..127 covers all 128 rows
    b2s[tid] = g_b2[col0 + tid];

    // ---- cp.async: chunk c (K cols c*32..c*32+31) -> ring stage s ----
    // 128 threads: each issues 8 A + 8 B float4 copies per chunk.
    const float4* Ag = reinterpret_cast<const float4*>(A + (size_t)row0 * DDIM);
    const float4* Bg = reinterpret_cast<const float4*>(B + (size_t)col0 * DDIM);
    const int rL = tid >> 3;        // base row (0..15), +i*16
    const int qL = tid & 7;         // float4 within 32-float chunk row
    #define ISSUE_CHUNK(c, s)                                                 \
        do {                                                                  \
            uint32_t aDst = SA + (uint32_t)((s) * RING_F) * 4;                \
            uint32_t bDst = aDst + 4096 * 4;                                  \
            _Pragma("unroll")                                                 \
            for (int i = 0; i < 8; i++) {                                     \
                int r = rL + i * 16;                                          \
                int idx = r * 32 + ((qL * 4) ^ ((r & 7) << 2));               \
                cp_async16(aDst + idx * 4, Ag + (size_t)r * 32 + (c) * 8 + qL);\
                cp_async16(bDst + idx * 4, Bg + (size_t)r * 32 + (c) * 8 + qL);\
            }                                                                 \
            CP_COMMIT();                                                      \
        } while (0)

    ISSUE_CHUNK(0, 0);
    ISSUE_CHUNK(1, 1);
    ISSUE_CHUNK(2, 2);

    // ---- warp tiling: 2(m) x 2(n); warp tile 64x64 ----
    const int mb = (wid & 1) * 64;
    const int nb = (wid >> 1) * 64;

    const int rA_l = lane & 15;
    const int dkA  = (lane >> 4) << 2;
    const int rB_l = (lane & 7) + ((lane >> 4) << 3);
    const int dkB  = ((lane >> 3) & 1) << 2;

    uint32_t aRowOff[4], bRowOff[4];
    int aXc[4], bXc[4];
    #pragma unroll
    for (int mt = 0; mt < 4; mt++) {
        int r = mb + mt * 16 + rA_l;
        aRowOff[mt] = (uint32_t)r * 128;
        aXc[mt]     = (r & 7) << 2;
    }
    #pragma unroll
    for (int q = 0; q < 4; q++) {
        int r = nb + q * 16 + rB_l;
        bRowOff[q] = 4096 * 4 + (uint32_t)r * 128;
        bXc[q]     = (r & 7) << 2;
    }

    float acc[4][8][4];
    #pragma unroll
    for (int mt = 0; mt < 4; mt++)
        #pragma unroll
        for (int nt = 0; nt < 8; nt++)
            #pragma unroll
            for (int e = 0; e < 4; e++) acc[mt][nt][e] = 0.0f;

    uint32_t af[4][4];
    uint32_t bf[8][2];

    // s = RING STAGE index (0..2), independent of chunk number.
    #define CHUNK_MMA(s)                                                      \
        do {                                                                  \
            uint32_t stBase = SA + (uint32_t)((s) * RING_F) * 4;              \
            _Pragma("unroll")                                                 \
            for (int ks = 0; ks < 4; ks++) {                                  \
                int kk = ks << 3;                                             \
                _Pragma("unroll")                                             \
                for (int mt = 0; mt < 4; mt++)                                \
                    ldsm_x4(af[mt], stBase + aRowOff[mt] +                    \
                            ((((kk | dkA) ^ aXc[mt])) << 2));                 \
                _Pragma("unroll")                                             \
                for (int q = 0; q < 4; q++) {                                 \
                    uint32_t t[4];                                            \
                    ldsm_x4(t, stBase + bRowOff[q] +                          \
                            ((((kk | dkB) ^ bXc[q])) << 2));                  \
                    bf[q * 2 + 0][0] = t[0];                                  \
                    bf[q * 2 + 0][1] = t[1];                                  \
                    bf[q * 2 + 1][0] = t[2];                                  \
                    bf[q * 2 + 1][1] = t[3];                                  \
                }                                                             \
                _Pragma("unroll")                                             \
                for (int mt = 0; mt < 4; mt++)                                \
                    _Pragma("unroll")                                         \
                    for (int nt = 0; nt < 8; nt++)                            \
                        mma_tf32(acc[mt][nt], af[mt], bf[nt]);                \
            }                                                                 \
        } while (0)

    CP_WAIT(2); __syncthreads();   // chunk 0 resident (stage 0)
    CHUNK_MMA(0);
    __syncthreads();               // all warps done reading stage 0
    ISSUE_CHUNK(3, 0);             // chunk 3 -> stage 0
    CP_WAIT(2); __syncthreads();   // chunk 1 resident (stage 1)
    CHUNK_MMA(1);
    CP_WAIT(1); __syncthreads();   // chunk 2 resident (stage 2)
    CHUNK_MMA(2);
    CP_WAIT(0); __syncthreads();   // chunk 3 resident (stage 0)
    CHUNK_MMA(0);
    #undef CHUNK_MMA
    #undef ISSUE_CHUNK

    // ---- epilogue: stage -> conflict-free smem -> coalesced STG.128 ----
    __syncthreads();               // done with ring; reuse as staging
    float* stg = smem + wid * (16 * STG_STRIDE);

    const int cl   = 4 * (lane & 15);
    const int rsel = lane >> 4;
    const float4 b2v = *reinterpret_cast<const float4*>(&b2s[nb + cl]);
    const int xw = ((g >> 2) & 1) << 2;

    #pragma unroll
    for (int mt = 0; mt < 4; mt++) {
        #pragma unroll
        for (int nt = 0; nt < 8; nt++) {
            int c = (nt * 8 + 2 * tig) ^ xw;
            *reinterpret_cast<float2*>(&stg[g * STG_STRIDE + c]) =
                make_float2(acc[mt][nt][0], acc[mt][nt][1]);
            *reinterpret_cast<float2*>(&stg[(g + 8) * STG_STRIDE + c]) =
                make_float2(acc[mt][nt][2], acc[mt][nt][3]);
        }
        __syncwarp();
        #pragma unroll
        for (int rr = 0; rr < 8; rr++) {
            int r = rr * 2 + rsel;
            int xorv = ((r >> 2) & 1) << 2;
            float4 v = *reinterpret_cast<const float4*>(
                &stg[r * STG_STRIDE + (cl ^ xorv)]);
            float a2r = a2s[mb + mt * 16 + r];
            float4 o;
            o.x = -fast_sqrt(fmaxf(fmaf(-2.0f, v.x, a2r + b2v.x), 0.0f));
            o.y = -fast_sqrt(fmaxf(fmaf(-2.0f, v.y, a2r + b2v.y), 0.0f));
            o.z = -fast_sqrt(fmaxf(fmaf(-2.0f, v.z, a2r + b2v.z), 0.0f));
            o.w = -fast_sqrt(fmaxf(fmaf(-2.0f, v.w, a2r + b2v.w), 0.0f));
            *reinterpret_cast<float4*>(
                &out[(size_t)(row0 + mb + mt * 16 + r) * M + (col0 + nb + cl)])
                = o;
        }
        __syncwarp();
    }
}

extern "C" void kernel_launch(void* const* d_in, const int* in_sizes, int n_in,
                              void* d_out, int out_size) {
    const float* A = (const float*)d_in[0];   // z_anc [N,128]
    const float* B = (const float*)d_in[1];   // z_pos_neg [M,128]
    float* out = (float*)d_out;

    const int N = in_sizes[0] / DDIM;
    const int M = in_sizes[1] / DDIM;

    // First call is the (non-captured) correctness run; capture-safe.
    static bool attr_ok = [] {
        cudaFuncSetAttribute(dist_mma_kernel,
                             cudaFuncAttributeMaxDynamicSharedMemorySize,
                             SMEM_BYTES);
        return true;
    }();
    (void)attr_ok;

    int totalRows = N + M;
    norms_kernel<<<(totalRows + 7) / 8, 256>>>(A, B, N, M);

    dim3 grid(M / TN, N / TM);
    dist_mma_kernel<<<grid, 128, SMEM_BYTES>>>(A, B, out, N, M);
}